// round 14
// baseline (speedup 1.0000x reference)
#include <cuda_runtime.h>
#include <cuda_fp16.h>
#include <math.h>

#define Bz 4
#define Nn 4096
#define Cin 128
#define Cout 128
#define Kk 10
#define Ll 50
#define Ne 65536
#define TBtot (Ll * Bz)   // 200
#define RNN_BLOCKS 128
#define RNN_THREADS 512

// smem layout for k_rnn_mma (bytes)
#define WS_STRIDE 4112                  // 4096 + 16 pad (conflict-free)
#define SM_WS (32 * WS_STRIDE)          // 131584
#define SM_DP (16 * 32 * 8 * 4)         // 16384
#define SM_ST 128                       // hq staging
#define SM_RNN (SM_WS + SM_DP + SM_ST)  // 148096

// ---------------- scratch (static device globals; no allocs) ----------------
__device__ __align__(16) float  g_filt[2 * Bz * Nn * Cout];  // 16 MB
__device__ __align__(16) float  g_y[2][Bz * Nn * Cout];      // 16 MB
__device__ __align__(16) float  g_res[Bz * Nn * Cout];       // 8 MB
__device__ __align__(16) float  g_gih[TBtot * Nn];           // [t][b][i]
__device__ __align__(16) signed char g_hq[2 * 4 * Nn];       // ping-pong h int8 [buf][b][node]
__device__ __align__(16) float  g_hf[4 * Nn];                // final h fp32 [b][node]
__device__ unsigned int g_flag[RNN_BLOCKS];                  // per-block step flags

// ---------------- helpers ----------------
__device__ __forceinline__ float gelu_exact(float x) {
    return 0.5f * x * (1.0f + erff(x * 0.7071067811865476f));
}

__device__ __forceinline__ float2 ffma2(float2 a, float2 b, float2 c) {
    unsigned long long au = *reinterpret_cast<unsigned long long*>(&a);
    unsigned long long bu = *reinterpret_cast<unsigned long long*>(&b);
    unsigned long long cu = *reinterpret_cast<unsigned long long*>(&c);
    unsigned long long du;
    asm("fma.rn.f32x2 %0, %1, %2, %3;" : "=l"(du) : "l"(au), "l"(bu), "l"(cu));
    return *reinterpret_cast<float2*>(&du);
}

__device__ __forceinline__ unsigned int ldcg_u32(const unsigned int* p) {
    unsigned int v;
    asm volatile("ld.global.cg.u32 %0, [%1];" : "=r"(v) : "l"(p));
    return v;
}

__device__ __forceinline__ unsigned int ld_acq(const unsigned int* p) {
    unsigned int v;
    asm volatile("ld.acquire.gpu.global.u32 %0, [%1];" : "=r"(v) : "l"(p));
    return v;
}

__device__ __forceinline__ void st_release(unsigned int* p, unsigned int v) {
    asm volatile("st.release.gpu.global.u32 [%0], %1;" :: "l"(p), "r"(v) : "memory");
}

__device__ __forceinline__ void mma_s8(int* d,
                                       unsigned int a0, unsigned int a1,
                                       unsigned int a2, unsigned int a3,
                                       unsigned int b0, unsigned int b1) {
    asm volatile(
        "mma.sync.aligned.m16n8k32.row.col.s32.s8.s8.s32 "
        "{%0,%1,%2,%3}, {%4,%5,%6,%7}, {%8,%9}, {%0,%1,%2,%3};"
        : "+r"(d[0]), "+r"(d[1]), "+r"(d[2]), "+r"(d[3])
        : "r"(a0), "r"(a1), "r"(a2), "r"(a3), "r"(b0), "r"(b1));
}

__device__ __forceinline__ int q8(float v, float s) {
    int x = __float2int_rn(v * s);
    return max(-127, min(127, x));
}

// ---------------- zero kernel: g_y (both) + g_res ----------------
__global__ void k_zero_all() {
    int i = blockIdx.x * blockDim.x + threadIdx.x;   // 1,048,576 threads
    float4 z = make_float4(0.f, 0.f, 0.f, 0.f);
    ((float4*)g_y)[i] = z;
    if (i < Bz * Nn * Cout / 4) ((float4*)g_res)[i] = z;
}

// ---------------- filt = fea @ W_l : 8 rows/warp register blocking ----------------
__global__ void k_gemm_filt(const float* __restrict__ fea,
                            const float* __restrict__ W1,
                            const float* __restrict__ W2) {
    extern __shared__ float4 Ws[];  // [128 c][32 lane-f4] = 64 KB
    const float4* W = (const float4*)(blockIdx.y ? W2 : W1);
    for (int i = threadIdx.x; i < Cin * Cout / 4; i += blockDim.x) Ws[i] = W[i];
    __syncthreads();

    int warp = threadIdx.x >> 5, lane = threadIdx.x & 31;
    int rowbase = (blockIdx.x * 8 + warp) * 8;
    const float4* f4 = (const float4*)fea + (size_t)rowbase * (Cin / 4);

    float2 acc[8][2];
#pragma unroll
    for (int r = 0; r < 8; r++) { acc[r][0] = make_float2(0.f, 0.f); acc[r][1] = make_float2(0.f, 0.f); }

    for (int c4 = 0; c4 < Cin / 4; c4++) {
        float4 fv[8];
#pragma unroll
        for (int r = 0; r < 8; r++) fv[r] = __ldg(f4 + r * (Cin / 4) + c4);
#pragma unroll
        for (int j = 0; j < 4; j++) {
            float4 w = Ws[(c4 * 4 + j) * 32 + lane];
            float2 wlo = make_float2(w.x, w.y), whi = make_float2(w.z, w.w);
#pragma unroll
            for (int r = 0; r < 8; r++) {
                float s = (j == 0) ? fv[r].x : (j == 1) ? fv[r].y : (j == 2) ? fv[r].z : fv[r].w;
                float2 ss = make_float2(s, s);
                acc[r][0] = ffma2(ss, wlo, acc[r][0]);
                acc[r][1] = ffma2(ss, whi, acc[r][1]);
            }
        }
    }

    float* out = g_filt + (size_t)blockIdx.y * Bz * Nn * Cout;
#pragma unroll
    for (int r = 0; r < 8; r++) {
        float4 o = make_float4(acc[r][0].x, acc[r][0].y, acc[r][1].x, acc[r][1].y);
        ((float4*)(out + (size_t)(rowbase + r) * Cout))[lane] = o;
    }
}

// ---------------- merged COO spmm: both layers, one-shot blocks ----------------
__global__ void k_spmm2(const int* __restrict__ idx0, const float* __restrict__ val0,
                        const int* __restrict__ idx1, const float* __restrict__ val1,
                        const float* __restrict__ d0, const float* __restrict__ d1,
                        int pass) {
    int g = blockIdx.x * blockDim.x + threadIdx.x;
    int w = g >> 5, lane = g & 31;           // w in [0, 2*Bz*Ne)
    int l = w >> 18;                          // Bz*Ne = 2^18
    int b = (w >> 16) & 3;
    int e = w & (Ne - 1);

    const int* idx = l ? idx1 : idx0;
    const float* val = l ? val1 : val0;
    const int* ib = idx + (size_t)b * 2 * Ne;
    int r = ib[e];
    int c = ib[Ne + e];
    float v = val[(size_t)b * Ne + e];

    const float* X;
    float* Y;
    if (pass == 0) {
        X = g_filt + (size_t)l * Bz * Nn * Cout;
        Y = g_y[l];
    } else {
        v *= __ldg((l ? d1 : d0) + c);
        X = g_y[l];
        Y = g_res;
    }
    float4 xv = ((const float4*)(X + ((size_t)b * Nn + c) * Cout))[lane];
    float4 add = make_float4(v * xv.x, v * xv.y, v * xv.z, v * xv.w);
    atomicAdd(((float4*)(Y + ((size_t)b * Nn + r) * Cout)) + lane, add);
}

// ---------------- gih: tiled GEMM; block(0,0) resets flags ----------------
__global__ void k_gih(const int* __restrict__ joblst,
                      const float* __restrict__ item_emb,
                      const float* __restrict__ W_ih,
                      const float* __restrict__ b_ih,
                      const float* __restrict__ b_hh) {
    if (blockIdx.x == 0 && blockIdx.y == 0 && threadIdx.x < RNN_BLOCKS)
        g_flag[threadIdx.x] = 0u;
    extern __shared__ float sm[];
    float* As = sm;                   // [128][132]
    float* Es = sm + 128 * 132;       // [128][68]
    int tid = threadIdx.x, lane = tid & 31, warp = tid >> 5;
    int i0 = blockIdx.x * 128, tb0 = blockIdx.y * 64;

#pragma unroll 4
    for (int r = 0; r < 16; r++) {
        int il = warp * 16 + r;
        float4 w = __ldg((const float4*)(W_ih + (size_t)(i0 + il) * Cin) + lane);
        As[(4 * lane + 0) * 132 + il] = w.x;
        As[(4 * lane + 1) * 132 + il] = w.y;
        As[(4 * lane + 2) * 132 + il] = w.z;
        As[(4 * lane + 3) * 132 + il] = w.w;
    }
#pragma unroll 4
    for (int r = 0; r < 8; r++) {
        int tbl = warp * 8 + r;
        int tb = tb0 + tbl;
        int j = 0;
        if (tb < TBtot) { int t = tb >> 2, b = tb & 3; j = joblst[b * Ll + t]; }
        float4 e = __ldg((const float4*)(item_emb + (size_t)j * Cout) + lane);
        Es[(4 * lane + 0) * 68 + tbl] = e.x;
        Es[(4 * lane + 1) * 68 + tbl] = e.y;
        Es[(4 * lane + 2) * 68 + tbl] = e.z;
        Es[(4 * lane + 3) * 68 + tbl] = e.w;
    }
    __syncthreads();

    int ti = lane * 4;
    int tt = warp * 8;
    float2 acc[4][4];
#pragma unroll
    for (int ii = 0; ii < 4; ii++)
#pragma unroll
        for (int p = 0; p < 4; p++) acc[ii][p] = make_float2(0.f, 0.f);

    for (int c = 0; c < 128; c++) {
        float4 a = ((const float4*)(As + c * 132))[lane];
        const float4* er = (const float4*)(Es + c * 68) + (tt >> 2);
        float4 e0 = er[0], e1 = er[1];
        float2 ep[4] = { {e0.x, e0.y}, {e0.z, e0.w}, {e1.x, e1.y}, {e1.z, e1.w} };
        float av[4] = { a.x, a.y, a.z, a.w };
#pragma unroll
        for (int ii = 0; ii < 4; ii++) {
            float2 aa = make_float2(av[ii], av[ii]);
#pragma unroll
            for (int p = 0; p < 4; p++) acc[ii][p] = ffma2(aa, ep[p], acc[ii][p]);
        }
    }

    float4 bi = *(const float4*)(b_ih + i0 + ti);
    float4 bh = *(const float4*)(b_hh + i0 + ti);
    bi.x += bh.x; bi.y += bh.y; bi.z += bh.z; bi.w += bh.w;

#pragma unroll
    for (int p = 0; p < 4; p++) {
        int tb = tb0 + tt + 2 * p;
        if (tb < TBtot) {
            float4 v = make_float4(acc[0][p].x + bi.x, acc[1][p].x + bi.y,
                                   acc[2][p].x + bi.z, acc[3][p].x + bi.w);
            *(float4*)(g_gih + (size_t)tb * Nn + i0 + ti) = v;
        }
        if (tb + 1 < TBtot) {
            float4 v = make_float4(acc[0][p].y + bi.x, acc[1][p].y + bi.y,
                                   acc[2][p].y + bi.z, acc[3][p].y + bi.w);
            *(float4*)(g_gih + (size_t)(tb + 1) * Nn + i0 + ti) = v;
        }
    }
}

// ---------------- persistent RNN: flag-wave sync, B fragments direct from L2 ----------------
// 128 blocks x 512 thr; block owns rows [32*bid, 32*bid+32). Warp w covers nodes [256w, 256w+256),
// produced by blocks 8w..8w+7 — warp waits only on those 8 flags.
__global__ void __launch_bounds__(RNN_THREADS, 1) k_rnn_mma(const float* __restrict__ Whh) {
    extern __shared__ unsigned char smraw[];
    unsigned char* Ws = smraw;                        // [32][WS_STRIDE] s8
    int* Dp = (int*)(smraw + SM_WS);                  // [16 warp][32 row][8 col] s32
    unsigned char* stage = smraw + SM_WS + SM_DP;     // [4 b][32 row] bytes
    unsigned int* Ws32 = (unsigned int*)Ws;

    int tid = threadIdx.x, warp = tid >> 5, lane = tid & 31;
    int row0 = blockIdx.x * 32;
    int g = lane >> 2, q = lane & 3;
    bool bact = (g < 4);

    // prologue: quantize W slice into smem
    for (int idx = tid; idx < 32 * 1024; idx += RNN_THREADS) {
        int r = idx >> 10, c4 = idx & 1023;
        float4 w = __ldg((const float4*)Whh + (size_t)(row0 + r) * (Nn / 4) + c4);
        int q0 = q8(w.x, 8192.f), q1 = q8(w.y, 8192.f);
        int q2 = q8(w.z, 8192.f), q3 = q8(w.w, 8192.f);
        Ws32[r * (WS_STRIDE / 4) + c4] =
            (q0 & 255) | ((q1 & 255) << 8) | ((q2 & 255) << 16) | ((q3 & 255) << 24);
    }
    __syncthreads();

    const float inv_scale = 1.f / (8192.f * 127.f);
    int myrow = tid >> 2, myb = tid & 3;     // reduce-phase mapping (tid < 128)
    int kbase = warp * 256;                  // node offset this warp consumes

    for (int t = 0; t < Ll; t++) {
        // prefetch gih (independent of flags)
        float gval = 0.f;
        if (tid < 128)
            gval = __ldg(g_gih + (size_t)t * Bz * Nn + myb * Nn + row0 + myrow);

        if (t > 0) {
            // wait for this warp's 8 producer blocks to publish h_t
            if (lane < 8) {
                const unsigned int* fp = &g_flag[warp * 8 + lane];
                while (ld_acq(fp) < (unsigned int)t) { }
            }
            __syncwarp();

            // B fragments direct from L2 (slot t&1); g>=4 lanes use zeros
            const unsigned int* hb = (const unsigned int*)
                (g_hq + (t & 1) * 4 * Nn + (g & 3) * Nn + kbase + q * 4);
            unsigned int bf[8][2];
#pragma unroll
            for (int kt = 0; kt < 8; kt++) {
                unsigned int v0 = ldcg_u32(hb + kt * 8);       // +32 B per kt
                unsigned int v1 = ldcg_u32(hb + kt * 8 + 4);   // +16 B
                bf[kt][0] = bact ? v0 : 0u;
                bf[kt][1] = bact ? v1 : 0u;
            }

            int d0[4] = {0, 0, 0, 0}, d1[4] = {0, 0, 0, 0};
#pragma unroll
            for (int kt = 0; kt < 8; kt++) {
                int ko = kbase + kt * 32 + q * 4;
                unsigned int a0 = *(const unsigned int*)(Ws + g * WS_STRIDE + ko);
                unsigned int a1 = *(const unsigned int*)(Ws + (g + 8) * WS_STRIDE + ko);
                unsigned int a2 = *(const unsigned int*)(Ws + g * WS_STRIDE + ko + 16);
                unsigned int a3 = *(const unsigned int*)(Ws + (g + 8) * WS_STRIDE + ko + 16);
                mma_s8(d0, a0, a1, a2, a3, bf[kt][0], bf[kt][1]);
                unsigned int c0 = *(const unsigned int*)(Ws + (g + 16) * WS_STRIDE + ko);
                unsigned int c1 = *(const unsigned int*)(Ws + (g + 24) * WS_STRIDE + ko);
                unsigned int c2 = *(const unsigned int*)(Ws + (g + 16) * WS_STRIDE + ko + 16);
                unsigned int c3 = *(const unsigned int*)(Ws + (g + 24) * WS_STRIDE + ko + 16);
                mma_s8(d1, c0, c1, c2, c3, bf[kt][0], bf[kt][1]);
            }
            int* dpw = Dp + warp * 256;
            dpw[g * 8 + 2 * q] = d0[0];        dpw[g * 8 + 2 * q + 1] = d0[1];
            dpw[(g + 8) * 8 + 2 * q] = d0[2];  dpw[(g + 8) * 8 + 2 * q + 1] = d0[3];
            dpw[(g + 16) * 8 + 2 * q] = d1[0]; dpw[(g + 16) * 8 + 2 * q + 1] = d1[1];
            dpw[(g + 24) * 8 + 2 * q] = d1[2]; dpw[(g + 24) * 8 + 2 * q + 1] = d1[3];
        }
        __syncthreads();

        if (tid < 128) {
            float x = gval;
            if (t > 0) {
                int s = 0;
#pragma unroll
                for (int w = 0; w < 16; w++) s += Dp[w * 256 + myrow * 8 + myb];
                x += (float)s * inv_scale;
            }
            float h = tanhf(x);
            stage[myb * 32 + myrow] = (signed char)__float2int_rn(h * 127.f);
            if (t == Ll - 1) g_hf[myb * Nn + row0 + myrow] = h;
        }
        __syncthreads();

        // warp 0: coalesced hq publication + release flag
        if (warp == 0) {
            int b = lane >> 3, w4 = lane & 7;
            unsigned int word = ((const unsigned int*)stage)[lane];   // [b][w4]
            *(unsigned int*)(g_hq + ((t + 1) & 1) * 4 * Nn + b * Nn + row0 + w4 * 4) = word;
            __syncwarp();
            if (lane == 0) st_release(&g_flag[blockIdx.x], (unsigned int)(t + 1));
        }
        __syncthreads();   // stage reused next step
    }
}

// ---------------- epilogue ----------------
__global__ void k_epi(const float* __restrict__ dW, const float* __restrict__ db,
                      float* __restrict__ out) {
    __shared__ float dWs[Kk * Cout];
    __shared__ float dbs[Kk];
    for (int i = threadIdx.x; i < Kk * Cout; i += blockDim.x) dWs[i] = dW[i];
    if (threadIdx.x < Kk) dbs[threadIdx.x] = db[threadIdx.x];
    __syncthreads();

    int warp = threadIdx.x >> 5, lane = threadIdx.x & 31;
    int gw = blockIdx.x * (blockDim.x >> 5) + warp;  // = b*Nn + n
    if (gw >= Bz * Nn) return;
    int b = gw >> 12;
    int n = gw & (Nn - 1);

    float4 r = ((const float4*)(g_res + (size_t)gw * Cout))[lane];
    float eh = gelu_exact(g_hf[b * Nn + n]);

#pragma unroll
    for (int k = 0; k < Kk; k++) {
        const float4* w4 = (const float4*)(dWs + k * Cout);
        float4 w = w4[lane];
        float p = r.x * w.x + r.y * w.y + r.z * w.z + r.w * w.w;
#pragma unroll
        for (int off = 16; off; off >>= 1) p += __shfl_xor_sync(0xffffffffu, p, off);
        if (lane == 0) {
            float s = gelu_exact(p + dbs[k]);
            float v = s * eh;
            out[(size_t)gw * Kk + k] = 1.0f / (1.0f + expf(-v));
        }
    }
}

// ---------------- launch ----------------
extern "C" void kernel_launch(void* const* d_in, const int* in_sizes, int n_in,
                              void* d_out, int out_size) {
    const int*   phi1_idx     = (const int*)d_in[0];
    const float* phi1_val     = (const float*)d_in[1];
    const int*   phi1_inv_idx = (const int*)d_in[2];
    const float* phi1_inv_val = (const float*)d_in[3];
    const int*   phi2_idx     = (const int*)d_in[4];
    const float* phi2_val     = (const float*)d_in[5];
    const int*   phi2_inv_idx = (const int*)d_in[6];
    const float* phi2_inv_val = (const float*)d_in[7];
    const float* fea          = (const float*)d_in[8];
    const int*   joblst       = (const int*)d_in[9];
    const float* W1           = (const float*)d_in[10];
    const float* d1           = (const float*)d_in[11];
    const float* W2           = (const float*)d_in[12];
    const float* d2           = (const float*)d_in[13];
    const float* W_ih         = (const float*)d_in[14];
    const float* W_hh         = (const float*)d_in[15];
    const float* b_ih         = (const float*)d_in[16];
    const float* b_hh         = (const float*)d_in[17];
    const float* dense_W      = (const float*)d_in[18];
    const float* dense_b      = (const float*)d_in[19];
    const float* item_emb     = (const float*)d_in[20];
    float*       out          = (float*)d_out;

    static cudaStream_t s2 = nullptr;
    static cudaEvent_t ev0 = nullptr, ev2 = nullptr;
    if (!s2) {
        cudaStreamCreateWithFlags(&s2, cudaStreamNonBlocking);
        cudaEventCreateWithFlags(&ev0, cudaEventDisableTiming);
        cudaEventCreateWithFlags(&ev2, cudaEventDisableTiming);
        cudaFuncSetAttribute(k_gemm_filt, cudaFuncAttributeMaxDynamicSharedMemorySize, 65536);
        cudaFuncSetAttribute(k_gih, cudaFuncAttributeMaxDynamicSharedMemorySize,
                             (128 * 132 + 128 * 68) * 4);
        cudaFuncSetAttribute(k_rnn_mma, cudaFuncAttributeMaxDynamicSharedMemorySize, SM_RNN);
    }

    // fork point
    cudaEventRecord(ev0, 0);
    cudaStreamWaitEvent(s2, ev0, 0);

    // ---- s2: entire conv chain (zero -> gemm -> spmm x2) ----
    k_zero_all<<<4096, 256, 0, s2>>>();
    k_gemm_filt<<<dim3(256, 2), 256, 65536, s2>>>(fea, W1, W2);
    k_spmm2<<<65536, 256, 0, s2>>>(phi1_inv_idx, phi1_inv_val, phi2_inv_idx, phi2_inv_val,
                                   nullptr, nullptr, 0);
    k_spmm2<<<65536, 256, 0, s2>>>(phi1_idx, phi1_val, phi2_idx, phi2_val, d1, d2, 1);
    cudaEventRecord(ev2, s2);

    // ---- main: RNN chain (gih resets flags, then flag-wave RNN) ----
    k_gih<<<dim3(32, 4), 256, (128 * 132 + 128 * 68) * 4>>>(joblst, item_emb, W_ih, b_ih, b_hh);
    k_rnn_mma<<<RNN_BLOCKS, RNN_THREADS, SM_RNN>>>(W_hh);

    // ---- join + epilogue ----
    cudaStreamWaitEvent(0, ev2, 0);
    k_epi<<<(Bz * Nn) / 8, 256>>>(dense_W, dense_b, out);
}

// round 15
// speedup vs baseline: 1.6300x; 1.6300x over previous
#include <cuda_runtime.h>
#include <cuda_fp16.h>
#include <math.h>

#define Bz 4
#define Nn 4096
#define Cin 128
#define Cout 128
#define Kk 10
#define Ll 50
#define Ne 65536
#define TBtot (Ll * Bz)   // 200
#define RNN_BLOCKS 128
#define RNN_THREADS 512

// smem layout for k_rnn_mma (bytes)
#define WS_STRIDE 4112                  // 4096 + 16 pad (conflict-free)
#define SM_WS (32 * WS_STRIDE)          // 131584
#define SM_BS (8 * WS_STRIDE)           // 32896
#define SM_DP (16 * 32 * 8 * 4)         // 16384
#define SM_RNN (SM_WS + SM_BS + SM_DP)  // 180864

// ---------------- scratch (static device globals; no allocs) ----------------
__device__ __align__(16) float  g_filt[2 * Bz * Nn * Cout];  // 16 MB
__device__ __align__(16) float  g_y[2][Bz * Nn * Cout];      // 16 MB
__device__ __align__(16) float  g_res[Bz * Nn * Cout];       // 8 MB
__device__ __align__(16) float  g_gih[TBtot * Nn];           // [t][b][i]
__device__ __align__(16) signed char g_hq[2 * 4 * Nn];       // ping-pong h int8 [buf][b][node]
__device__ __align__(16) float  g_hf[4 * Nn];                // final h fp32 [b][node]
__device__ unsigned int g_bar;                               // grid barrier counter

// ---------------- helpers ----------------
__device__ __forceinline__ float gelu_exact(float x) {
    return 0.5f * x * (1.0f + erff(x * 0.7071067811865476f));
}

__device__ __forceinline__ float2 ffma2(float2 a, float2 b, float2 c) {
    unsigned long long au = *reinterpret_cast<unsigned long long*>(&a);
    unsigned long long bu = *reinterpret_cast<unsigned long long*>(&b);
    unsigned long long cu = *reinterpret_cast<unsigned long long*>(&c);
    unsigned long long du;
    asm("fma.rn.f32x2 %0, %1, %2, %3;" : "=l"(du) : "l"(au), "l"(bu), "l"(cu));
    return *reinterpret_cast<float2*>(&du);
}

__device__ __forceinline__ uint4 ldcg_u4(const uint4* p) {
    uint4 v;
    asm volatile("ld.global.cg.v4.u32 {%0,%1,%2,%3}, [%4];"
                 : "=r"(v.x), "=r"(v.y), "=r"(v.z), "=r"(v.w) : "l"(p));
    return v;
}

__device__ __forceinline__ unsigned int ld_acq(const unsigned int* p) {
    unsigned int v;
    asm volatile("ld.acquire.gpu.global.u32 %0, [%1];" : "=r"(v) : "l"(p));
    return v;
}

__device__ __forceinline__ void red_release_add(unsigned int* p, unsigned int v) {
    asm volatile("red.release.gpu.global.add.u32 [%0], %1;" :: "l"(p), "r"(v) : "memory");
}

__device__ __forceinline__ void mma_s8(int* d,
                                       unsigned int a0, unsigned int a1,
                                       unsigned int a2, unsigned int a3,
                                       unsigned int b0, unsigned int b1) {
    asm volatile(
        "mma.sync.aligned.m16n8k32.row.col.s32.s8.s8.s32 "
        "{%0,%1,%2,%3}, {%4,%5,%6,%7}, {%8,%9}, {%0,%1,%2,%3};"
        : "+r"(d[0]), "+r"(d[1]), "+r"(d[2]), "+r"(d[3])
        : "r"(a0), "r"(a1), "r"(a2), "r"(a3), "r"(b0), "r"(b1));
}

__device__ __forceinline__ int q8(float v, float s) {
    int x = __float2int_rn(v * s);
    return max(-127, min(127, x));
}

// ---------------- zero kernel: g_y (both) + g_res ----------------
__global__ void k_zero_all() {
    int i = blockIdx.x * blockDim.x + threadIdx.x;   // 1,048,576 threads
    float4 z = make_float4(0.f, 0.f, 0.f, 0.f);
    ((float4*)g_y)[i] = z;
    if (i < Bz * Nn * Cout / 4) ((float4*)g_res)[i] = z;
}

// ---------------- filt = fea @ W_l : 8 rows/warp register blocking ----------------
__global__ void k_gemm_filt(const float* __restrict__ fea,
                            const float* __restrict__ W1,
                            const float* __restrict__ W2) {
    extern __shared__ float4 Ws[];  // [128 c][32 lane-f4] = 64 KB
    const float4* W = (const float4*)(blockIdx.y ? W2 : W1);
    for (int i = threadIdx.x; i < Cin * Cout / 4; i += blockDim.x) Ws[i] = W[i];
    __syncthreads();

    int warp = threadIdx.x >> 5, lane = threadIdx.x & 31;
    int rowbase = (blockIdx.x * 8 + warp) * 8;
    const float4* f4 = (const float4*)fea + (size_t)rowbase * (Cin / 4);

    float2 acc[8][2];
#pragma unroll
    for (int r = 0; r < 8; r++) { acc[r][0] = make_float2(0.f, 0.f); acc[r][1] = make_float2(0.f, 0.f); }

    for (int c4 = 0; c4 < Cin / 4; c4++) {
        float4 fv[8];
#pragma unroll
        for (int r = 0; r < 8; r++) fv[r] = __ldg(f4 + r * (Cin / 4) + c4);
#pragma unroll
        for (int j = 0; j < 4; j++) {
            float4 w = Ws[(c4 * 4 + j) * 32 + lane];
            float2 wlo = make_float2(w.x, w.y), whi = make_float2(w.z, w.w);
#pragma unroll
            for (int r = 0; r < 8; r++) {
                float s = (j == 0) ? fv[r].x : (j == 1) ? fv[r].y : (j == 2) ? fv[r].z : fv[r].w;
                float2 ss = make_float2(s, s);
                acc[r][0] = ffma2(ss, wlo, acc[r][0]);
                acc[r][1] = ffma2(ss, whi, acc[r][1]);
            }
        }
    }

    float* out = g_filt + (size_t)blockIdx.y * Bz * Nn * Cout;
#pragma unroll
    for (int r = 0; r < 8; r++) {
        float4 o = make_float4(acc[r][0].x, acc[r][0].y, acc[r][1].x, acc[r][1].y);
        ((float4*)(out + (size_t)(rowbase + r) * Cout))[lane] = o;
    }
}

// ---------------- merged COO spmm: both layers, one-shot blocks ----------------
__global__ void k_spmm2(const int* __restrict__ idx0, const float* __restrict__ val0,
                        const int* __restrict__ idx1, const float* __restrict__ val1,
                        const float* __restrict__ d0, const float* __restrict__ d1,
                        int pass) {
    int g = blockIdx.x * blockDim.x + threadIdx.x;
    int w = g >> 5, lane = g & 31;           // w in [0, 2*Bz*Ne)
    int l = w >> 18;                          // Bz*Ne = 2^18
    int b = (w >> 16) & 3;
    int e = w & (Ne - 1);

    const int* idx = l ? idx1 : idx0;
    const float* val = l ? val1 : val0;
    const int* ib = idx + (size_t)b * 2 * Ne;
    int r = ib[e];
    int c = ib[Ne + e];
    float v = val[(size_t)b * Ne + e];

    const float* X;
    float* Y;
    if (pass == 0) {
        X = g_filt + (size_t)l * Bz * Nn * Cout;
        Y = g_y[l];
    } else {
        v *= __ldg((l ? d1 : d0) + c);
        X = g_y[l];
        Y = g_res;
    }
    float4 xv = ((const float4*)(X + ((size_t)b * Nn + c) * Cout))[lane];
    float4 add = make_float4(v * xv.x, v * xv.y, v * xv.z, v * xv.w);
    atomicAdd(((float4*)(Y + ((size_t)b * Nn + r) * Cout)) + lane, add);
}

// ---------------- gih: tiled GEMM; block(0,0) resets grid barrier ----------------
__global__ void k_gih(const int* __restrict__ joblst,
                      const float* __restrict__ item_emb,
                      const float* __restrict__ W_ih,
                      const float* __restrict__ b_ih,
                      const float* __restrict__ b_hh) {
    if (blockIdx.x == 0 && blockIdx.y == 0 && threadIdx.x == 0) g_bar = 0u;
    extern __shared__ float sm[];
    float* As = sm;                   // [128][132]
    float* Es = sm + 128 * 132;       // [128][68]
    int tid = threadIdx.x, lane = tid & 31, warp = tid >> 5;
    int i0 = blockIdx.x * 128, tb0 = blockIdx.y * 64;

#pragma unroll 4
    for (int r = 0; r < 16; r++) {
        int il = warp * 16 + r;
        float4 w = __ldg((const float4*)(W_ih + (size_t)(i0 + il) * Cin) + lane);
        As[(4 * lane + 0) * 132 + il] = w.x;
        As[(4 * lane + 1) * 132 + il] = w.y;
        As[(4 * lane + 2) * 132 + il] = w.z;
        As[(4 * lane + 3) * 132 + il] = w.w;
    }
#pragma unroll 4
    for (int r = 0; r < 8; r++) {
        int tbl = warp * 8 + r;
        int tb = tb0 + tbl;
        int j = 0;
        if (tb < TBtot) { int t = tb >> 2, b = tb & 3; j = joblst[b * Ll + t]; }
        float4 e = __ldg((const float4*)(item_emb + (size_t)j * Cout) + lane);
        Es[(4 * lane + 0) * 68 + tbl] = e.x;
        Es[(4 * lane + 1) * 68 + tbl] = e.y;
        Es[(4 * lane + 2) * 68 + tbl] = e.z;
        Es[(4 * lane + 3) * 68 + tbl] = e.w;
    }
    __syncthreads();

    int ti = lane * 4;
    int tt = warp * 8;
    float2 acc[4][4];
#pragma unroll
    for (int ii = 0; ii < 4; ii++)
#pragma unroll
        for (int p = 0; p < 4; p++) acc[ii][p] = make_float2(0.f, 0.f);

    for (int c = 0; c < 128; c++) {
        float4 a = ((const float4*)(As + c * 132))[lane];
        const float4* er = (const float4*)(Es + c * 68) + (tt >> 2);
        float4 e0 = er[0], e1 = er[1];
        float2 ep[4] = { {e0.x, e0.y}, {e0.z, e0.w}, {e1.x, e1.y}, {e1.z, e1.w} };
        float av[4] = { a.x, a.y, a.z, a.w };
#pragma unroll
        for (int ii = 0; ii < 4; ii++) {
            float2 aa = make_float2(av[ii], av[ii]);
#pragma unroll
            for (int p = 0; p < 4; p++) acc[ii][p] = ffma2(aa, ep[p], acc[ii][p]);
        }
    }

    float4 bi = *(const float4*)(b_ih + i0 + ti);
    float4 bh = *(const float4*)(b_hh + i0 + ti);
    bi.x += bh.x; bi.y += bh.y; bi.z += bh.z; bi.w += bh.w;

#pragma unroll
    for (int p = 0; p < 4; p++) {
        int tb = tb0 + tt + 2 * p;
        if (tb < TBtot) {
            float4 v = make_float4(acc[0][p].x + bi.x, acc[1][p].x + bi.y,
                                   acc[2][p].x + bi.z, acc[3][p].x + bi.w);
            *(float4*)(g_gih + (size_t)tb * Nn + i0 + ti) = v;
        }
        if (tb + 1 < TBtot) {
            float4 v = make_float4(acc[0][p].y + bi.x, acc[1][p].y + bi.y,
                                   acc[2][p].y + bi.z, acc[3][p].y + bi.w);
            *(float4*)(g_gih + (size_t)(tb + 1) * Nn + i0 + ti) = v;
        }
    }
}

// ---------------- persistent RNN: int8 MMA, 512 threads, shfl-assembled publish ----------------
__global__ void __launch_bounds__(RNN_THREADS, 1) k_rnn_mma(const float* __restrict__ Whh) {
    extern __shared__ unsigned char smraw[];
    unsigned char* Ws = smraw;                        // [32][WS_STRIDE] s8
    unsigned char* Bs = smraw + SM_WS;                // [8][WS_STRIDE] s8
    int* Dp = (int*)(smraw + SM_WS + SM_BS);          // [16 warp][32 row][8 col] s32
    unsigned int* Ws32 = (unsigned int*)Ws;
    unsigned int* Bs32 = (unsigned int*)Bs;

    int tid = threadIdx.x, warp = tid >> 5, lane = tid & 31;
    int row0 = blockIdx.x * 32;
    int g = lane >> 2, q = lane & 3;

    for (int i = tid; i < 8 * (WS_STRIDE / 4); i += RNN_THREADS) Bs32[i] = 0;
    for (int idx = tid; idx < 32 * 1024; idx += RNN_THREADS) {
        int r = idx >> 10, c4 = idx & 1023;
        float4 w = __ldg((const float4*)Whh + (size_t)(row0 + r) * (Nn / 4) + c4);
        int q0 = q8(w.x, 8192.f), q1 = q8(w.y, 8192.f);
        int q2 = q8(w.z, 8192.f), q3 = q8(w.w, 8192.f);
        Ws32[r * (WS_STRIDE / 4) + c4] =
            (q0 & 255) | ((q1 & 255) << 8) | ((q2 & 255) << 16) | ((q3 & 255) << 24);
    }
    __syncthreads();

    const float inv_scale = 1.f / (8192.f * 127.f);
    int myrow = tid >> 2, myb = tid & 3;   // reduce-phase mapping (tid < 128)

    for (int t = 0; t < Ll; t++) {
        // prefetch gih (independent of barrier-protected h)
        float gval = 0.f;
        if (tid < 128)
            gval = __ldg(g_gih + (size_t)t * Bz * Nn + myb * Nn + row0 + myrow);

        if (t > 0) {
            const uint4* src = (const uint4*)g_hq + (t & 1) * 1024;
            for (int i = tid; i < 1024; i += RNN_THREADS) {
                int n = i >> 8, w4 = i & 255;
                ((uint4*)(Bs + n * WS_STRIDE))[w4] = ldcg_u4(src + i);
            }
            __syncthreads();

            int d0[4] = {0, 0, 0, 0}, d1[4] = {0, 0, 0, 0};
            int kbase = warp * 8;
#pragma unroll
            for (int kt = 0; kt < 8; kt++) {
                int ko = (kbase + kt) * 32 + q * 4;
                unsigned int a0 = *(const unsigned int*)(Ws + g * WS_STRIDE + ko);
                unsigned int a1 = *(const unsigned int*)(Ws + (g + 8) * WS_STRIDE + ko);
                unsigned int a2 = *(const unsigned int*)(Ws + g * WS_STRIDE + ko + 16);
                unsigned int a3 = *(const unsigned int*)(Ws + (g + 8) * WS_STRIDE + ko + 16);
                unsigned int b0 = *(const unsigned int*)(Bs + g * WS_STRIDE + ko);
                unsigned int b1 = *(const unsigned int*)(Bs + g * WS_STRIDE + ko + 16);
                mma_s8(d0, a0, a1, a2, a3, b0, b1);
                unsigned int c0 = *(const unsigned int*)(Ws + (g + 16) * WS_STRIDE + ko);
                unsigned int c1 = *(const unsigned int*)(Ws + (g + 24) * WS_STRIDE + ko);
                unsigned int c2 = *(const unsigned int*)(Ws + (g + 16) * WS_STRIDE + ko + 16);
                unsigned int c3 = *(const unsigned int*)(Ws + (g + 24) * WS_STRIDE + ko + 16);
                mma_s8(d1, c0, c1, c2, c3, b0, b1);
            }
            int* dpw = Dp + warp * 256;
            dpw[g * 8 + 2 * q] = d0[0];        dpw[g * 8 + 2 * q + 1] = d0[1];
            dpw[(g + 8) * 8 + 2 * q] = d0[2];  dpw[(g + 8) * 8 + 2 * q + 1] = d0[3];
            dpw[(g + 16) * 8 + 2 * q] = d1[0]; dpw[(g + 16) * 8 + 2 * q + 1] = d1[1];
            dpw[(g + 24) * 8 + 2 * q] = d1[2]; dpw[(g + 24) * 8 + 2 * q + 1] = d1[3];
        }
        __syncthreads();

        // reduce + in-register word assembly + direct publish (warps 0-3)
        if (tid < 128) {
            float x = gval;
            if (t > 0) {
                int s = 0;
#pragma unroll
                for (int w = 0; w < 16; w++) s += Dp[w * 256 + myrow * 8 + myb];
                x += (float)s * inv_scale;
            }
            float h = tanhf(x);
            if (t == Ll - 1) g_hf[myb * Nn + row0 + myrow] = h;

            // byte for (row=myrow, b=myb); assemble 4-row words via shfl
            unsigned int ub = (unsigned int)(unsigned char)(signed char)__float2int_rn(h * 127.f);
            int srcbase = lane & 0x13;                      // 16j + b
            unsigned int w0 = __shfl_sync(0xffffffffu, ub, srcbase);
            unsigned int w1 = __shfl_sync(0xffffffffu, ub, srcbase | 4);
            unsigned int w2 = __shfl_sync(0xffffffffu, ub, srcbase | 8);
            unsigned int w3 = __shfl_sync(0xffffffffu, ub, srcbase | 12);
            if ((lane & 0x0C) == 0) {                       // 8 writer lanes/warp
                unsigned int word = w0 | (w1 << 8) | (w2 << 16) | (w3 << 24);
                int b = lane & 3, j = (lane >> 4) & 1;
                int node = row0 + warp * 8 + 4 * j;         // warp = tid>>5 (0..3)
                *(unsigned int*)(g_hq + ((t + 1) & 1) * 4 * Nn + b * Nn + node) = word;
            }
        }

        // grid barrier: release-RED arrive (orders the STGs via syncthreads), acquire poll
        __syncthreads();
        if (tid == 0) {
            red_release_add(&g_bar, 1u);
            unsigned int target = (unsigned int)RNN_BLOCKS * (t + 1);
            while (ld_acq(&g_bar) < target) { }
        }
        __syncthreads();
    }
}

// ---------------- epilogue ----------------
__global__ void k_epi(const float* __restrict__ dW, const float* __restrict__ db,
                      float* __restrict__ out) {
    __shared__ float dWs[Kk * Cout];
    __shared__ float dbs[Kk];
    for (int i = threadIdx.x; i < Kk * Cout; i += blockDim.x) dWs[i] = dW[i];
    if (threadIdx.x < Kk) dbs[threadIdx.x] = db[threadIdx.x];
    __syncthreads();

    int warp = threadIdx.x >> 5, lane = threadIdx.x & 31;
    int gw = blockIdx.x * (blockDim.x >> 5) + warp;  // = b*Nn + n
    if (gw >= Bz * Nn) return;
    int b = gw >> 12;
    int n = gw & (Nn - 1);

    float4 r = ((const float4*)(g_res + (size_t)gw * Cout))[lane];
    float eh = gelu_exact(g_hf[b * Nn + n]);

#pragma unroll
    for (int k = 0; k < Kk; k++) {
        const float4* w4 = (const float4*)(dWs + k * Cout);
        float4 w = w4[lane];
        float p = r.x * w.x + r.y * w.y + r.z * w.z + r.w * w.w;
#pragma unroll
        for (int off = 16; off; off >>= 1) p += __shfl_xor_sync(0xffffffffu, p, off);
        if (lane == 0) {
            float s = gelu_exact(p + dbs[k]);
            float v = s * eh;
            out[(size_t)gw * Kk + k] = 1.0f / (1.0f + expf(-v));
        }
    }
}

// ---------------- launch ----------------
extern "C" void kernel_launch(void* const* d_in, const int* in_sizes, int n_in,
                              void* d_out, int out_size) {
    const int*   phi1_idx     = (const int*)d_in[0];
    const float* phi1_val     = (const float*)d_in[1];
    const int*   phi1_inv_idx = (const int*)d_in[2];
    const float* phi1_inv_val = (const float*)d_in[3];
    const int*   phi2_idx     = (const int*)d_in[4];
    const float* phi2_val     = (const float*)d_in[5];
    const int*   phi2_inv_idx = (const int*)d_in[6];
    const float* phi2_inv_val = (const float*)d_in[7];
    const float* fea          = (const float*)d_in[8];
    const int*   joblst       = (const int*)d_in[9];
    const float* W1           = (const float*)d_in[10];
    const float* d1           = (const float*)d_in[11];
    const float* W2           = (const float*)d_in[12];
    const float* d2           = (const float*)d_in[13];
    const float* W_ih         = (const float*)d_in[14];
    const float* W_hh         = (const float*)d_in[15];
    const float* b_ih         = (const float*)d_in[16];
    const float* b_hh         = (const float*)d_in[17];
    const float* dense_W      = (const float*)d_in[18];
    const float* dense_b      = (const float*)d_in[19];
    const float* item_emb     = (const float*)d_in[20];
    float*       out          = (float*)d_out;

    static cudaStream_t s2 = nullptr;
    static cudaEvent_t ev0 = nullptr, ev2 = nullptr;
    if (!s2) {
        cudaStreamCreateWithFlags(&s2, cudaStreamNonBlocking);
        cudaEventCreateWithFlags(&ev0, cudaEventDisableTiming);
        cudaEventCreateWithFlags(&ev2, cudaEventDisableTiming);
        cudaFuncSetAttribute(k_gemm_filt, cudaFuncAttributeMaxDynamicSharedMemorySize, 65536);
        cudaFuncSetAttribute(k_gih, cudaFuncAttributeMaxDynamicSharedMemorySize,
                             (128 * 132 + 128 * 68) * 4);
        cudaFuncSetAttribute(k_rnn_mma, cudaFuncAttributeMaxDynamicSharedMemorySize, SM_RNN);
    }

    // fork point
    cudaEventRecord(ev0, 0);
    cudaStreamWaitEvent(s2, ev0, 0);

    // ---- s2: entire conv chain (zero -> gemm -> spmm x2) ----
    k_zero_all<<<4096, 256, 0, s2>>>();
    k_gemm_filt<<<dim3(256, 2), 256, 65536, s2>>>(fea, W1, W2);
    k_spmm2<<<65536, 256, 0, s2>>>(phi1_inv_idx, phi1_inv_val, phi2_inv_idx, phi2_inv_val,
                                   nullptr, nullptr, 0);
    k_spmm2<<<65536, 256, 0, s2>>>(phi1_idx, phi1_val, phi2_idx, phi2_val, d1, d2, 1);
    cudaEventRecord(ev2, s2);

    // ---- main: RNN chain (gih resets g_bar, then persistent RNN) ----
    k_gih<<<dim3(32, 4), 256, (128 * 132 + 128 * 68) * 4>>>(joblst, item_emb, W_ih, b_ih, b_hh);
    k_rnn_mma<<<RNN_BLOCKS, RNN_THREADS, SM_RNN>>>(W_hh);

    // ---- join + epilogue ----
    cudaStreamWaitEvent(0, ev2, 0);
    k_epi<<<(Bz * Nn) / 8, 256>>>(dense_W, dense_b, out);
}

// round 16
// speedup vs baseline: 1.6870x; 1.0349x over previous
#include <cuda_runtime.h>
#include <cuda_fp16.h>
#include <math.h>

#define Bz 4
#define Nn 4096
#define Cin 128
#define Cout 128
#define Kk 10
#define Ll 50
#define Ne 65536
#define TBtot (Ll * Bz)   // 200
#define RNN_BLOCKS 128
#define RNN_THREADS 512
#define NBAR 16           // tree-barrier counters (8 arrivals each)

// smem layout for k_rnn_mma (bytes)
#define WS_STRIDE 4112                  // 4096 + 16 pad (conflict-free)
#define SM_WS (32 * WS_STRIDE)          // 131584
#define SM_BS (8 * WS_STRIDE)           // 32896
#define SM_DP (16 * 32 * 8 * 4)         // 16384
#define SM_RNN (SM_WS + SM_BS + SM_DP)  // 180864

// ---------------- scratch (static device globals; no allocs) ----------------
__device__ __align__(16) float  g_filt[2 * Bz * Nn * Cout];  // 16 MB
__device__ __align__(16) float  g_y[2][Bz * Nn * Cout];      // 16 MB
__device__ __align__(16) float  g_res[Bz * Nn * Cout];       // 8 MB
__device__ __align__(16) float  g_res2[Bz * Nn * Kk];        // 655 KB: gelu(res@dW^T+db)
__device__ __align__(16) float  g_gih[TBtot * Nn];           // [t][b][i]
__device__ __align__(16) signed char g_hq[2 * 4 * Nn];       // ping-pong h int8 [buf][b][node]
__device__ __align__(16) float  g_hf[4 * Nn];                // final h fp32 [b][node]
__device__ __align__(256) unsigned int g_bars[NBAR][64];     // counters 256 B apart

// ---------------- helpers ----------------
__device__ __forceinline__ float gelu_exact(float x) {
    return 0.5f * x * (1.0f + erff(x * 0.7071067811865476f));
}

__device__ __forceinline__ float2 ffma2(float2 a, float2 b, float2 c) {
    unsigned long long au = *reinterpret_cast<unsigned long long*>(&a);
    unsigned long long bu = *reinterpret_cast<unsigned long long*>(&b);
    unsigned long long cu = *reinterpret_cast<unsigned long long*>(&c);
    unsigned long long du;
    asm("fma.rn.f32x2 %0, %1, %2, %3;" : "=l"(du) : "l"(au), "l"(bu), "l"(cu));
    return *reinterpret_cast<float2*>(&du);
}

__device__ __forceinline__ uint4 ldcg_u4(const uint4* p) {
    uint4 v;
    asm volatile("ld.global.cg.v4.u32 {%0,%1,%2,%3}, [%4];"
                 : "=r"(v.x), "=r"(v.y), "=r"(v.z), "=r"(v.w) : "l"(p));
    return v;
}

__device__ __forceinline__ unsigned int ld_acq(const unsigned int* p) {
    unsigned int v;
    asm volatile("ld.acquire.gpu.global.u32 %0, [%1];" : "=r"(v) : "l"(p));
    return v;
}

__device__ __forceinline__ void red_release_add(unsigned int* p, unsigned int v) {
    asm volatile("red.release.gpu.global.add.u32 [%0], %1;" :: "l"(p), "r"(v) : "memory");
}

__device__ __forceinline__ void mma_s8(int* d,
                                       unsigned int a0, unsigned int a1,
                                       unsigned int a2, unsigned int a3,
                                       unsigned int b0, unsigned int b1) {
    asm volatile(
        "mma.sync.aligned.m16n8k32.row.col.s32.s8.s8.s32 "
        "{%0,%1,%2,%3}, {%4,%5,%6,%7}, {%8,%9}, {%0,%1,%2,%3};"
        : "+r"(d[0]), "+r"(d[1]), "+r"(d[2]), "+r"(d[3])
        : "r"(a0), "r"(a1), "r"(a2), "r"(a3), "r"(b0), "r"(b1));
}

__device__ __forceinline__ int q8(float v, float s) {
    int x = __float2int_rn(v * s);
    return max(-127, min(127, x));
}

// ---------------- zero kernel: g_y (both) + g_res ----------------
__global__ void k_zero_all() {
    int i = blockIdx.x * blockDim.x + threadIdx.x;   // 1,048,576 threads
    float4 z = make_float4(0.f, 0.f, 0.f, 0.f);
    ((float4*)g_y)[i] = z;
    if (i < Bz * Nn * Cout / 4) ((float4*)g_res)[i] = z;
}

// ---------------- filt = fea @ W_l : 8 rows/warp register blocking ----------------
__global__ void k_gemm_filt(const float* __restrict__ fea,
                            const float* __restrict__ W1,
                            const float* __restrict__ W2) {
    extern __shared__ float4 Ws[];  // [128 c][32 lane-f4] = 64 KB
    const float4* W = (const float4*)(blockIdx.y ? W2 : W1);
    for (int i = threadIdx.x; i < Cin * Cout / 4; i += blockDim.x) Ws[i] = W[i];
    __syncthreads();

    int warp = threadIdx.x >> 5, lane = threadIdx.x & 31;
    int rowbase = (blockIdx.x * 8 + warp) * 8;
    const float4* f4 = (const float4*)fea + (size_t)rowbase * (Cin / 4);

    float2 acc[8][2];
#pragma unroll
    for (int r = 0; r < 8; r++) { acc[r][0] = make_float2(0.f, 0.f); acc[r][1] = make_float2(0.f, 0.f); }

    for (int c4 = 0; c4 < Cin / 4; c4++) {
        float4 fv[8];
#pragma unroll
        for (int r = 0; r < 8; r++) fv[r] = __ldg(f4 + r * (Cin / 4) + c4);
#pragma unroll
        for (int j = 0; j < 4; j++) {
            float4 w = Ws[(c4 * 4 + j) * 32 + lane];
            float2 wlo = make_float2(w.x, w.y), whi = make_float2(w.z, w.w);
#pragma unroll
            for (int r = 0; r < 8; r++) {
                float s = (j == 0) ? fv[r].x : (j == 1) ? fv[r].y : (j == 2) ? fv[r].z : fv[r].w;
                float2 ss = make_float2(s, s);
                acc[r][0] = ffma2(ss, wlo, acc[r][0]);
                acc[r][1] = ffma2(ss, whi, acc[r][1]);
            }
        }
    }

    float* out = g_filt + (size_t)blockIdx.y * Bz * Nn * Cout;
#pragma unroll
    for (int r = 0; r < 8; r++) {
        float4 o = make_float4(acc[r][0].x, acc[r][0].y, acc[r][1].x, acc[r][1].y);
        ((float4*)(out + (size_t)(rowbase + r) * Cout))[lane] = o;
    }
}

// ---------------- merged COO spmm: both layers, one-shot blocks ----------------
__global__ void k_spmm2(const int* __restrict__ idx0, const float* __restrict__ val0,
                        const int* __restrict__ idx1, const float* __restrict__ val1,
                        const float* __restrict__ d0, const float* __restrict__ d1,
                        int pass) {
    int g = blockIdx.x * blockDim.x + threadIdx.x;
    int w = g >> 5, lane = g & 31;           // w in [0, 2*Bz*Ne)
    int l = w >> 18;                          // Bz*Ne = 2^18
    int b = (w >> 16) & 3;
    int e = w & (Ne - 1);

    const int* idx = l ? idx1 : idx0;
    const float* val = l ? val1 : val0;
    const int* ib = idx + (size_t)b * 2 * Ne;
    int r = ib[e];
    int c = ib[Ne + e];
    float v = val[(size_t)b * Ne + e];

    const float* X;
    float* Y;
    if (pass == 0) {
        X = g_filt + (size_t)l * Bz * Nn * Cout;
        Y = g_y[l];
    } else {
        v *= __ldg((l ? d1 : d0) + c);
        X = g_y[l];
        Y = g_res;
    }
    float4 xv = ((const float4*)(X + ((size_t)b * Nn + c) * Cout))[lane];
    float4 add = make_float4(v * xv.x, v * xv.y, v * xv.z, v * xv.w);
    atomicAdd(((float4*)(Y + ((size_t)b * Nn + r) * Cout)) + lane, add);
}

// ---------------- gih: tiled GEMM; block(0,0) resets tree-barrier counters ----------------
__global__ void k_gih(const int* __restrict__ joblst,
                      const float* __restrict__ item_emb,
                      const float* __restrict__ W_ih,
                      const float* __restrict__ b_ih,
                      const float* __restrict__ b_hh) {
    if (blockIdx.x == 0 && blockIdx.y == 0 && threadIdx.x < NBAR)
        g_bars[threadIdx.x][0] = 0u;
    extern __shared__ float sm[];
    float* As = sm;                   // [128][132]
    float* Es = sm + 128 * 132;       // [128][68]
    int tid = threadIdx.x, lane = tid & 31, warp = tid >> 5;
    int i0 = blockIdx.x * 128, tb0 = blockIdx.y * 64;

#pragma unroll 4
    for (int r = 0; r < 16; r++) {
        int il = warp * 16 + r;
        float4 w = __ldg((const float4*)(W_ih + (size_t)(i0 + il) * Cin) + lane);
        As[(4 * lane + 0) * 132 + il] = w.x;
        As[(4 * lane + 1) * 132 + il] = w.y;
        As[(4 * lane + 2) * 132 + il] = w.z;
        As[(4 * lane + 3) * 132 + il] = w.w;
    }
#pragma unroll 4
    for (int r = 0; r < 8; r++) {
        int tbl = warp * 8 + r;
        int tb = tb0 + tbl;
        int j = 0;
        if (tb < TBtot) { int t = tb >> 2, b = tb & 3; j = joblst[b * Ll + t]; }
        float4 e = __ldg((const float4*)(item_emb + (size_t)j * Cout) + lane);
        Es[(4 * lane + 0) * 68 + tbl] = e.x;
        Es[(4 * lane + 1) * 68 + tbl] = e.y;
        Es[(4 * lane + 2) * 68 + tbl] = e.z;
        Es[(4 * lane + 3) * 68 + tbl] = e.w;
    }
    __syncthreads();

    int ti = lane * 4;
    int tt = warp * 8;
    float2 acc[4][4];
#pragma unroll
    for (int ii = 0; ii < 4; ii++)
#pragma unroll
        for (int p = 0; p < 4; p++) acc[ii][p] = make_float2(0.f, 0.f);

    for (int c = 0; c < 128; c++) {
        float4 a = ((const float4*)(As + c * 132))[lane];
        const float4* er = (const float4*)(Es + c * 68) + (tt >> 2);
        float4 e0 = er[0], e1 = er[1];
        float2 ep[4] = { {e0.x, e0.y}, {e0.z, e0.w}, {e1.x, e1.y}, {e1.z, e1.w} };
        float av[4] = { a.x, a.y, a.z, a.w };
#pragma unroll
        for (int ii = 0; ii < 4; ii++) {
            float2 aa = make_float2(av[ii], av[ii]);
#pragma unroll
            for (int p = 0; p < 4; p++) acc[ii][p] = ffma2(aa, ep[p], acc[ii][p]);
        }
    }

    float4 bi = *(const float4*)(b_ih + i0 + ti);
    float4 bh = *(const float4*)(b_hh + i0 + ti);
    bi.x += bh.x; bi.y += bh.y; bi.z += bh.z; bi.w += bh.w;

#pragma unroll
    for (int p = 0; p < 4; p++) {
        int tb = tb0 + tt + 2 * p;
        if (tb < TBtot) {
            float4 v = make_float4(acc[0][p].x + bi.x, acc[1][p].x + bi.y,
                                   acc[2][p].x + bi.z, acc[3][p].x + bi.w);
            *(float4*)(g_gih + (size_t)tb * Nn + i0 + ti) = v;
        }
        if (tb + 1 < TBtot) {
            float4 v = make_float4(acc[0][p].y + bi.x, acc[1][p].y + bi.y,
                                   acc[2][p].y + bi.z, acc[3][p].y + bi.w);
            *(float4*)(g_gih + (size_t)(tb + 1) * Nn + i0 + ti) = v;
        }
    }
}

// ---------------- persistent RNN: int8 MMA, tree barrier (16 counters x 8 arrivals) ----------------
__global__ void __launch_bounds__(RNN_THREADS, 1) k_rnn_mma(const float* __restrict__ Whh) {
    extern __shared__ unsigned char smraw[];
    unsigned char* Ws = smraw;                        // [32][WS_STRIDE] s8
    unsigned char* Bs = smraw + SM_WS;                // [8][WS_STRIDE] s8
    int* Dp = (int*)(smraw + SM_WS + SM_BS);          // [16 warp][32 row][8 col] s32
    unsigned int* Ws32 = (unsigned int*)Ws;
    unsigned int* Bs32 = (unsigned int*)Bs;

    int tid = threadIdx.x, warp = tid >> 5, lane = tid & 31;
    int row0 = blockIdx.x * 32;
    int g = lane >> 2, q = lane & 3;

    for (int i = tid; i < 8 * (WS_STRIDE / 4); i += RNN_THREADS) Bs32[i] = 0;
    for (int idx = tid; idx < 32 * 1024; idx += RNN_THREADS) {
        int r = idx >> 10, c4 = idx & 1023;
        float4 w = __ldg((const float4*)Whh + (size_t)(row0 + r) * (Nn / 4) + c4);
        int q0 = q8(w.x, 8192.f), q1 = q8(w.y, 8192.f);
        int q2 = q8(w.z, 8192.f), q3 = q8(w.w, 8192.f);
        Ws32[r * (WS_STRIDE / 4) + c4] =
            (q0 & 255) | ((q1 & 255) << 8) | ((q2 & 255) << 16) | ((q3 & 255) << 24);
    }
    __syncthreads();

    const float inv_scale = 1.f / (8192.f * 127.f);
    int myrow = tid >> 2, myb = tid & 3;   // reduce-phase mapping (tid < 128)
    unsigned int* mybar = &g_bars[blockIdx.x & (NBAR - 1)][0];

    for (int t = 0; t < Ll; t++) {
        // prefetch gih (independent of barrier-protected h)
        float gval = 0.f;
        if (tid < 128)
            gval = __ldg(g_gih + (size_t)t * Bz * Nn + myb * Nn + row0 + myrow);

        if (t > 0) {
            const uint4* src = (const uint4*)g_hq + (t & 1) * 1024;
            for (int i = tid; i < 1024; i += RNN_THREADS) {
                int n = i >> 8, w4 = i & 255;
                ((uint4*)(Bs + n * WS_STRIDE))[w4] = ldcg_u4(src + i);
            }
            __syncthreads();

            int d0[4] = {0, 0, 0, 0}, d1[4] = {0, 0, 0, 0};
            int kbase = warp * 8;
#pragma unroll
            for (int kt = 0; kt < 8; kt++) {
                int ko = (kbase + kt) * 32 + q * 4;
                unsigned int a0 = *(const unsigned int*)(Ws + g * WS_STRIDE + ko);
                unsigned int a1 = *(const unsigned int*)(Ws + (g + 8) * WS_STRIDE + ko);
                unsigned int a2 = *(const unsigned int*)(Ws + g * WS_STRIDE + ko + 16);
                unsigned int a3 = *(const unsigned int*)(Ws + (g + 8) * WS_STRIDE + ko + 16);
                unsigned int b0 = *(const unsigned int*)(Bs + g * WS_STRIDE + ko);
                unsigned int b1 = *(const unsigned int*)(Bs + g * WS_STRIDE + ko + 16);
                mma_s8(d0, a0, a1, a2, a3, b0, b1);
                unsigned int c0 = *(const unsigned int*)(Ws + (g + 16) * WS_STRIDE + ko);
                unsigned int c1 = *(const unsigned int*)(Ws + (g + 24) * WS_STRIDE + ko);
                unsigned int c2 = *(const unsigned int*)(Ws + (g + 16) * WS_STRIDE + ko + 16);
                unsigned int c3 = *(const unsigned int*)(Ws + (g + 24) * WS_STRIDE + ko + 16);
                mma_s8(d1, c0, c1, c2, c3, b0, b1);
            }
            int* dpw = Dp + warp * 256;
            dpw[g * 8 + 2 * q] = d0[0];        dpw[g * 8 + 2 * q + 1] = d0[1];
            dpw[(g + 8) * 8 + 2 * q] = d0[2];  dpw[(g + 8) * 8 + 2 * q + 1] = d0[3];
            dpw[(g + 16) * 8 + 2 * q] = d1[0]; dpw[(g + 16) * 8 + 2 * q + 1] = d1[1];
            dpw[(g + 24) * 8 + 2 * q] = d1[2]; dpw[(g + 24) * 8 + 2 * q + 1] = d1[3];
        }
        __syncthreads();

        // reduce + in-register word assembly + publish (warps 0-3)
        if (tid < 128) {
            float x = gval;
            if (t > 0) {
                int s = 0;
#pragma unroll
                for (int w = 0; w < 16; w++) s += Dp[w * 256 + myrow * 8 + myb];
                x += (float)s * inv_scale;
            }
            float h = tanhf(x);
            if (t == Ll - 1) {
                g_hf[myb * Nn + row0 + myrow] = h;   // final step: only hf needed
            } else {
                unsigned int ub = (unsigned int)(unsigned char)(signed char)__float2int_rn(h * 127.f);
                int srcbase = lane & 0x13;                      // 16j + b
                unsigned int w0 = __shfl_sync(0xffffffffu, ub, srcbase);
                unsigned int w1 = __shfl_sync(0xffffffffu, ub, srcbase | 4);
                unsigned int w2 = __shfl_sync(0xffffffffu, ub, srcbase | 8);
                unsigned int w3 = __shfl_sync(0xffffffffu, ub, srcbase | 12);
                if ((lane & 0x0C) == 0) {                       // 8 writer lanes/warp
                    unsigned int word = w0 | (w1 << 8) | (w2 << 16) | (w3 << 24);
                    int b = lane & 3, j = (lane >> 4) & 1;
                    int node = row0 + warp * 8 + 4 * j;
                    *(unsigned int*)(g_hq + ((t + 1) & 1) * 4 * Nn + b * Nn + node) = word;
                }
            }
        }

        if (t < Ll - 1) {
            // tree barrier: release-RED on own counter, 16-lane acquire poll
            __syncthreads();
            if (warp == 0) {
                if (lane == 0) red_release_add(mybar, 1u);
                unsigned int target = (unsigned int)(RNN_BLOCKS / NBAR) * (t + 1);
                if (lane < NBAR) {
                    const unsigned int* cp = &g_bars[lane][0];
                    while (ld_acq(cp) < target) { }
                }
            }
            __syncthreads();
        }
    }
}

// ---------------- epilogue stage 1 (no h): g_res2 = gelu(res @ dW^T + db) ----------------
__global__ void k_epi1(const float* __restrict__ dW, const float* __restrict__ db) {
    __shared__ float dWs[Kk * Cout];
    __shared__ float dbs[Kk];
    for (int i = threadIdx.x; i < Kk * Cout; i += blockDim.x) dWs[i] = dW[i];
    if (threadIdx.x < Kk) dbs[threadIdx.x] = db[threadIdx.x];
    __syncthreads();

    int warp = threadIdx.x >> 5, lane = threadIdx.x & 31;
    int gw = blockIdx.x * (blockDim.x >> 5) + warp;  // = b*Nn + n
    if (gw >= Bz * Nn) return;

    float4 r = ((const float4*)(g_res + (size_t)gw * Cout))[lane];

#pragma unroll
    for (int k = 0; k < Kk; k++) {
        const float4* w4 = (const float4*)(dWs + k * Cout);
        float4 w = w4[lane];
        float p = r.x * w.x + r.y * w.y + r.z * w.z + r.w * w.w;
#pragma unroll
        for (int off = 16; off; off >>= 1) p += __shfl_xor_sync(0xffffffffu, p, off);
        if (lane == 0) g_res2[(size_t)gw * Kk + k] = gelu_exact(p + dbs[k]);
    }
}

// ---------------- epilogue stage 2 (tiny): out = sigmoid(res2 * gelu(h)) ----------------
__global__ void k_epi2(float* __restrict__ out) {
    int i = blockIdx.x * blockDim.x + threadIdx.x;   // Bz*Nn threads
    float eh = gelu_exact(g_hf[i]);                  // g_hf layout = [b][n] = same as gw
#pragma unroll
    for (int k = 0; k < Kk; k++) {
        float v = g_res2[(size_t)i * Kk + k] * eh;
        out[(size_t)i * Kk + k] = 1.0f / (1.0f + expf(-v));
    }
}

// ---------------- launch ----------------
extern "C" void kernel_launch(void* const* d_in, const int* in_sizes, int n_in,
                              void* d_out, int out_size) {
    const int*   phi1_idx     = (const int*)d_in[0];
    const float* phi1_val     = (const float*)d_in[1];
    const int*   phi1_inv_idx = (const int*)d_in[2];
    const float* phi1_inv_val = (const float*)d_in[3];
    const int*   phi2_idx     = (const int*)d_in[4];
    const float* phi2_val     = (const float*)d_in[5];
    const int*   phi2_inv_idx = (const int*)d_in[6];
    const float* phi2_inv_val = (const float*)d_in[7];
    const float* fea          = (const float*)d_in[8];
    const int*   joblst       = (const int*)d_in[9];
    const float* W1           = (const float*)d_in[10];
    const float* d1           = (const float*)d_in[11];
    const float* W2           = (const float*)d_in[12];
    const float* d2           = (const float*)d_in[13];
    const float* W_ih         = (const float*)d_in[14];
    const float* W_hh         = (const float*)d_in[15];
    const float* b_ih         = (const float*)d_in[16];
    const float* b_hh         = (const float*)d_in[17];
    const float* dense_W      = (const float*)d_in[18];
    const float* dense_b      = (const float*)d_in[19];
    const float* item_emb     = (const float*)d_in[20];
    float*       out          = (float*)d_out;

    static cudaStream_t s2 = nullptr;
    static cudaEvent_t ev0 = nullptr, ev2 = nullptr;
    if (!s2) {
        cudaStreamCreateWithFlags(&s2, cudaStreamNonBlocking);
        cudaEventCreateWithFlags(&ev0, cudaEventDisableTiming);
        cudaEventCreateWithFlags(&ev2, cudaEventDisableTiming);
        cudaFuncSetAttribute(k_gemm_filt, cudaFuncAttributeMaxDynamicSharedMemorySize, 65536);
        cudaFuncSetAttribute(k_gih, cudaFuncAttributeMaxDynamicSharedMemorySize,
                             (128 * 132 + 128 * 68) * 4);
        cudaFuncSetAttribute(k_rnn_mma, cudaFuncAttributeMaxDynamicSharedMemorySize, SM_RNN);
    }

    // fork point
    cudaEventRecord(ev0, 0);
    cudaStreamWaitEvent(s2, ev0, 0);

    // ---- s2: conv chain (zero -> gemm -> spmm x2 -> epi stage 1) ----
    k_zero_all<<<4096, 256, 0, s2>>>();
    k_gemm_filt<<<dim3(256, 2), 256, 65536, s2>>>(fea, W1, W2);
    k_spmm2<<<65536, 256, 0, s2>>>(phi1_inv_idx, phi1_inv_val, phi2_inv_idx, phi2_inv_val,
                                   nullptr, nullptr, 0);
    k_spmm2<<<65536, 256, 0, s2>>>(phi1_idx, phi1_val, phi2_idx, phi2_val, d1, d2, 1);
    k_epi1<<<(Bz * Nn) / 8, 256, 0, s2>>>(dense_W, dense_b);
    cudaEventRecord(ev2, s2);

    // ---- main: RNN chain (gih resets counters, then persistent RNN) ----
    k_gih<<<dim3(32, 4), 256, (128 * 132 + 128 * 68) * 4>>>(joblst, item_emb, W_ih, b_ih, b_hh);
    k_rnn_mma<<<RNN_BLOCKS, RNN_THREADS, SM_RNN>>>(W_hh);

    // ---- join + tiny final epilogue ----
    cudaStreamWaitEvent(0, ev2, 0);
    k_epi2<<<(Bz * Nn) / 256, 256>>>(out);
}